// round 1
// baseline (speedup 1.0000x reference)
#include <cuda_runtime.h>
#include <cuda_bf16.h>
#include <math.h>

// Problem constants (fixed by reference setup_inputs)
#define BB 8
#define TT 16
#define CC 64
#define NN 4096          // H*W
#define KSEL 2048        // keep_k = N*(1-0.5)

// Scratch (device globals — no allocation allowed)
__device__ float g_partial[BB * TT * NN];            // sqrt(sum_c x^2) per (b,t,n), 2 MB
__device__ unsigned g_maskbits[BB * (NN / 32)];      // 1 bit per (b,n), 4 KB

// ---------------------------------------------------------------------------
// Kernel 1: per-(b,t,n) partial = sqrt(sum_c x[b,t,c,n]^2)
// 524288 threads, each does 64 coalesced loads (stride N between c).
// ---------------------------------------------------------------------------
__global__ void k_partial(const float* __restrict__ x) {
    int idx = blockIdx.x * blockDim.x + threadIdx.x;   // [0, B*T*N)
    int n  = idx & (NN - 1);
    int bt = idx >> 12;                                // b*T + t
    const float* p = x + (size_t)bt * CC * NN + n;
    float acc = 0.0f;
#pragma unroll
    for (int c = 0; c < CC; ++c) {
        float v = p[(size_t)c * NN];
        acc += v * v;
    }
    g_partial[idx] = sqrtf(acc);
}

// ---------------------------------------------------------------------------
// Kernel 2: per-batch exact top-K selection -> mask bits.
// One block of 1024 threads per batch. Thread j owns n = 4j..4j+3.
// Radix select on float bit pattern (positive floats are order-isomorphic to
// their uint bits). Ties broken by lowest index (matches jax.lax.top_k).
// ---------------------------------------------------------------------------
__device__ __forceinline__ int warp_sum(int v) {
#pragma unroll
    for (int d = 16; d; d >>= 1) v += __shfl_xor_sync(0xffffffffu, v, d);
    return v;
}

__global__ void __launch_bounds__(1024, 1) k_select() {
    __shared__ int s_red[33];
    __shared__ int s_warp[32];
    __shared__ unsigned s_mask[NN / 32];   // 128 words

    const int b    = blockIdx.x;
    const int j    = threadIdx.x;          // 0..1023
    const int lane = j & 31;
    const int wid  = j >> 5;

    // --- compute 4 scores per thread (deterministic: sequential over t) ---
    const float4* part = (const float4*)g_partial;
    float s0 = 0.f, s1 = 0.f, s2 = 0.f, s3 = 0.f;
#pragma unroll
    for (int t = 0; t < TT; ++t) {
        float4 f = part[(size_t)(b * TT + t) * (NN / 4) + j];
        s0 += f.x; s1 += f.y; s2 += f.z; s3 += f.w;
    }
    const float inv = 1.0f / (float)TT;
    unsigned u[4];
    u[0] = __float_as_uint(s0 * inv);
    u[1] = __float_as_uint(s1 * inv);
    u[2] = __float_as_uint(s2 * inv);
    u[3] = __float_as_uint(s3 * inv);

    // --- radix select: largest thr with count(u >= thr) >= KSEL ---
    unsigned thr = 0u;
    for (int bit = 30; bit >= 0; --bit) {
        unsigned cand = thr | (1u << bit);
        int cnt = (u[0] >= cand) + (u[1] >= cand) + (u[2] >= cand) + (u[3] >= cand);
        cnt = warp_sum(cnt);
        if (lane == 0) s_red[wid] = cnt;
        __syncthreads();
        if (wid == 0) {
            int t = s_red[lane];
            t = warp_sum(t);
            if (lane == 0) s_red[32] = t;
        }
        __syncthreads();
        int total = s_red[32];
        __syncthreads();
        if (total >= KSEL) thr = cand;
    }

    // --- count strictly-greater, then rank equals by index ---
    int gt = (u[0] > thr) + (u[1] > thr) + (u[2] > thr) + (u[3] > thr);
    {
        int c = warp_sum(gt);
        if (lane == 0) s_red[wid] = c;
        __syncthreads();
        if (wid == 0) {
            int t = s_red[lane];
            t = warp_sum(t);
            if (lane == 0) s_red[32] = t;
        }
        __syncthreads();
    }
    int n_greater = s_red[32];
    int need = KSEL - n_greater;       // equals to admit, lowest index first
    __syncthreads();

    // exclusive scan (over thread index) of per-thread equal-count
    int e = (u[0] == thr) + (u[1] == thr) + (u[2] == thr) + (u[3] == thr);
    int v = e;
#pragma unroll
    for (int d = 1; d < 32; d <<= 1) {
        int t = __shfl_up_sync(0xffffffffu, v, d);
        if (lane >= d) v += t;
    }
    if (lane == 31) s_warp[wid] = v;
    __syncthreads();
    if (wid == 0) {
        int w = s_warp[lane];
#pragma unroll
        for (int d = 1; d < 32; d <<= 1) {
            int t = __shfl_up_sync(0xffffffffu, w, d);
            if (lane >= d) w += t;
        }
        s_warp[lane] = w;
    }
    __syncthreads();
    int excl = v - e + (wid ? s_warp[wid - 1] : 0);

    // --- build mask nibble for n = 4j..4j+3 ---
    unsigned nib = 0;
    int r = excl;
#pragma unroll
    for (int i = 0; i < 4; ++i) {
        if (u[i] > thr) {
            nib |= 1u << i;
        } else if (u[i] == thr) {
            if (r < need) nib |= 1u << i;
            ++r;
        }
    }

    if (j < NN / 32) s_mask[j] = 0u;
    __syncthreads();
    atomicOr(&s_mask[j >> 3], nib << ((j & 7) * 4));
    __syncthreads();
    if (j < NN / 32) g_maskbits[b * (NN / 32) + j] = s_mask[j];
}

// ---------------------------------------------------------------------------
// Kernel 3: streaming masked copy, float4 granularity.
// Per batch: T*C*N = 2^22 floats = 2^20 float4 -> b = i >> 20.
// Mask array is 4 KB: L1-resident after first touches.
// ---------------------------------------------------------------------------
__global__ void k_mask(const float4* __restrict__ x4, float4* __restrict__ o4) {
    unsigned i = blockIdx.x * blockDim.x + threadIdx.x;   // [0, 8388608)
    int n4 = i & ((NN / 4) - 1);
    int b  = i >> 20;
    int n  = n4 << 2;
    unsigned mword = g_maskbits[(b << 7) + (n >> 5)];
    unsigned bits  = mword >> (n & 31);
    float4 v = x4[(size_t)i];
    v.x = (bits & 1u) ? v.x : 0.0f;
    v.y = (bits & 2u) ? v.y : 0.0f;
    v.z = (bits & 4u) ? v.z : 0.0f;
    v.w = (bits & 8u) ? v.w : 0.0f;
    o4[(size_t)i] = v;
}

// ---------------------------------------------------------------------------
extern "C" void kernel_launch(void* const* d_in, const int* in_sizes, int n_in,
                              void* d_out, int out_size) {
    const float* x = (const float*)d_in[0];
    float* out = (float*)d_out;

    // Kernel 1: B*T*N = 524288 threads
    k_partial<<<(BB * TT * NN) / 256, 256>>>(x);

    // Kernel 2: one 1024-thread block per batch
    k_select<<<BB, 1024>>>();

    // Kernel 3: 8388608 float4 elements
    k_mask<<<(BB * TT * CC * NN / 4) / 256, 256>>>(
        (const float4*)x, (float4*)out);
}